// round 6
// baseline (speedup 1.0000x reference)
#include <cuda_runtime.h>
#include <cuda_bf16.h>
#include <cstdint>

// RNN_438086664357: h_{t+1} = tanh(W [h_t ; x_t] + b)
// Round 6: persistent step kernel (128 resident CTAs, dataflow flags),
// W slice resident in smem; Z = x@Wx^T+b precomputed (R5 kernel).

#define TSTEPS 256
#define BATCH  256
#define DH     1024
#define DIN    1024
#define KTOT   2048
#define KC     64

typedef unsigned int u32;

// ---- persistent kernel smem layout ----
#define SM_WHI  0            // 8 panels x 8KB = 64KB
#define SM_WLO  65536        // 64KB
#define SM_A    131072       // 3 stages x (Ahi 8K + Alo 8K) = 48KB
#define ASTG    16384
#define SM_RED  180224       // 16KB reduction buffer
#define SM_MISC 196608       // role
#define SMEMP   196640

// precompute stage: Ahi 16K | Alo 16K | Whi 8K | Wlo 8K
#define SOFF2_ALO 16384
#define SOFF2_WHI 32768
#define SOFF2_WLO 40960
#define STG2      49152
#define SMEM2     (3 * STG2)

// ---- device scratch ----
__device__ __nv_bfloat16 g_xhi[(size_t)TSTEPS * BATCH * DIN];
__device__ __nv_bfloat16 g_xlo[(size_t)TSTEPS * BATCH * DIN];
__device__ __nv_bfloat16 g_whi[(size_t)DH * KTOT];
__device__ __nv_bfloat16 g_wlo[(size_t)DH * KTOT];
__device__ __nv_bfloat16 g_hhi[2 * (size_t)BATCH * DH];
__device__ __nv_bfloat16 g_hlo[2 * (size_t)BATCH * DH];
__device__ float g_Z[(size_t)TSTEPS * BATCH * DH];
__device__ float g_part[64 * 2 * 2 * 4096];   // tile, kh, stepparity
__device__ int   g_cnt[64];
__device__ int   g_flag[64];

__device__ __forceinline__ u32 s2u(const void* p) {
    u32 a;
    asm("{ .reg .u64 t; cvta.to.shared.u64 t, %1; cvt.u32.u64 %0, t; }"
        : "=r"(a) : "l"(p));
    return a;
}

#define CP16(sm, gp) asm volatile("cp.async.cg.shared.global [%0], [%1], 16;" :: "r"(sm), "l"(gp))
#define CP_COMMIT()  asm volatile("cp.async.commit_group;" ::: "memory")

__device__ __forceinline__ void ldsm4(u32 a, u32& r0, u32& r1, u32& r2, u32& r3) {
    asm volatile("ldmatrix.sync.aligned.m8n8.x4.shared.b16 {%0,%1,%2,%3}, [%4];"
                 : "=r"(r0), "=r"(r1), "=r"(r2), "=r"(r3) : "r"(a));
}

__device__ __forceinline__ void mma16816(float* c, const u32* a, u32 b0, u32 b1) {
    asm volatile(
        "mma.sync.aligned.m16n8k16.row.col.f32.bf16.bf16.f32 "
        "{%0,%1,%2,%3}, {%4,%5,%6,%7}, {%8,%9}, {%0,%1,%2,%3};"
        : "+f"(c[0]), "+f"(c[1]), "+f"(c[2]), "+f"(c[3])
        : "r"(a[0]), "r"(a[1]), "r"(a[2]), "r"(a[3]), "r"(b0), "r"(b1));
}

// ---- setup kernels ----
__global__ void split_w(const float* __restrict__ W) {
    int i = blockIdx.x * blockDim.x + threadIdx.x;
    float v = W[i];
    __nv_bfloat16 h = __float2bfloat16(v);
    g_whi[i] = h;
    g_wlo[i] = __float2bfloat16(v - __bfloat162float(h));
}

__global__ void split_x(const float* __restrict__ X) {
    size_t i = (size_t)blockIdx.x * blockDim.x + threadIdx.x;
    float v = X[i];
    __nv_bfloat16 h = __float2bfloat16(v);
    g_xhi[i] = h;
    g_xlo[i] = __float2bfloat16(v - __bfloat162float(h));
}

__global__ void init_h(float* __restrict__ out0) {
    int i = blockIdx.x * blockDim.x + threadIdx.x;
    out0[i] = 0.0f;
    __nv_bfloat16 z = __float2bfloat16(0.0f);
    g_hhi[i] = z;  g_hlo[i] = z;
    g_hhi[BATCH * DH + i] = z;  g_hlo[BATCH * DH + i] = z;
    if (i < 64) { g_cnt[i] = 0; g_flag[i] = 0; }
}

// ---- precompute Z = x @ Wx^T + b (unchanged from R5: tensor=67%) ----
__global__ void __launch_bounds__(256, 1)
precompute_z(const float* __restrict__ bias)
{
    extern __shared__ char smem[];
    const u32 sb = s2u(smem);
    const int tid = threadIdx.x, wid = tid >> 5, lane = tid & 31;
    const int wm = wid & 3, wn = wid >> 2;
    const int n0 = blockIdx.x * 64;
    const int mg = blockIdx.y * 128;

    auto load_chunk = [&](int c, int s) {
        const u32 st = sb + s * STG2;
        const int ko = c * KC;
        #pragma unroll
        for (int i = 0; i < 4; i++) {
            int unit = tid + i * 256;
            int r = unit >> 3, g = unit & 7;
            u32 so = (u32)(r * 128 + ((g ^ (r & 7)) * 16));
            size_t go = (size_t)(mg + r) * DIN + ko + g * 8;
            CP16(st + so,             g_xhi + go);
            CP16(st + SOFF2_ALO + so, g_xlo + go);
        }
        #pragma unroll
        for (int i = 0; i < 2; i++) {
            int unit = tid + i * 256;
            int r = unit >> 3, g = unit & 7;
            u32 so = (u32)(r * 128 + ((g ^ (r & 7)) * 16));
            size_t go = (size_t)(n0 + r) * KTOT + DH + ko + g * 8;
            CP16(st + SOFF2_WHI + so, g_whi + go);
            CP16(st + SOFF2_WLO + so, g_wlo + go);
        }
        CP_COMMIT();
    };

    float c0[32], c1[32], c2[32];
    #pragma unroll
    for (int i = 0; i < 32; i++) { c0[i] = 0.f; c1[i] = 0.f; c2[i] = 0.f; }

    load_chunk(0, 0);
    load_chunk(1, 1);
    for (int c = 0; c < 16; c++) {
        if (c < 15) asm volatile("cp.async.wait_group 1;" ::: "memory");
        else        asm volatile("cp.async.wait_group 0;" ::: "memory");
        __syncthreads();
        const u32 st = sb + (c % 3) * STG2;
        #pragma unroll
        for (int j = 0; j < 4; j++) {
            u32 ah[2][4], al[2][4], bh[8], bl[8];
            #pragma unroll
            for (int tm = 0; tm < 2; tm++) {
                int row = wm * 32 + tm * 16 + (lane & 15);
                int g = j * 2 + (lane >> 4);
                u32 so = (u32)(row * 128 + ((g ^ (row & 7)) * 16));
                ldsm4(st + so,             ah[tm][0], ah[tm][1], ah[tm][2], ah[tm][3]);
                ldsm4(st + SOFF2_ALO + so, al[tm][0], al[tm][1], al[tm][2], al[tm][3]);
            }
            int rB = wn * 32 + (lane & 7) + ((lane >> 4) & 1) * 8;
            int gB = j * 2 + ((lane >> 3) & 1);
            #pragma unroll
            for (int q = 0; q < 2; q++) {
                int r = rB + q * 16;
                u32 so = (u32)(r * 128 + ((gB ^ (r & 7)) * 16));
                ldsm4(st + SOFF2_WHI + so, bh[q*4+0], bh[q*4+1], bh[q*4+2], bh[q*4+3]);
                ldsm4(st + SOFF2_WLO + so, bl[q*4+0], bl[q*4+1], bl[q*4+2], bl[q*4+3]);
            }
            #pragma unroll
            for (int tm = 0; tm < 2; tm++)
                #pragma unroll
                for (int nt = 0; nt < 4; nt++) {
                    int o = tm * 16 + nt * 4;
                    mma16816(c0 + o, ah[tm], bh[nt*2], bh[nt*2+1]);
                    mma16816(c1 + o, al[tm], bh[nt*2], bh[nt*2+1]);
                    mma16816(c2 + o, ah[tm], bl[nt*2], bl[nt*2+1]);
                }
        }
        if (c + 2 < 16) load_chunk(c + 2, (c + 2) % 3);
    }

    #pragma unroll
    for (int tm = 0; tm < 2; tm++)
        #pragma unroll
        for (int nt = 0; nt < 4; nt++) {
            const int col = n0 + wn * 32 + nt * 8 + (lane & 3) * 2;
            const float b0 = __ldg(bias + col), b1 = __ldg(bias + col + 1);
            #pragma unroll
            for (int hf = 0; hf < 2; hf++) {
                const int row = mg + wm * 32 + tm * 16 + (lane >> 2) + hf * 8;
                const int o = tm * 16 + nt * 4 + hf * 2;
                float z0 = c0[o]   + c1[o]   + c2[o]   + b0;
                float z1 = c0[o+1] + c1[o+1] + c2[o+1] + b1;
                *(float2*)(g_Z + (size_t)row * DH + col) = make_float2(z0, z1);
            }
        }
}

// ---- persistent per-step engine ----
// grid 128 = kh(2) x m(4) x n(16); CTA tile (64m, 64n), K=512 per kh.
// 8 warps: wk = wid>>2 splits k16 steps; wq = wid&3 -> 2x2 m32n32 tiles.
__global__ void __launch_bounds__(256, 1)
rnn_persist(float* __restrict__ out)
{
    extern __shared__ char smem[];
    const u32 sb = s2u(smem);
    int* roleP = (int*)(smem + SM_MISC);
    const int tid = threadIdx.x, wid = tid >> 5, lane = tid & 31;
    const int wk = wid >> 2, wq = wid & 3;
    const int wm = wq & 1, wn = wq >> 1;
    const int bid = blockIdx.x;
    const int nI = bid & 15, mI = (bid >> 4) & 3, kh = bid >> 6;
    const int n0 = nI * 64, m0 = mI * 64, kb = kh * 512;
    const int tile = mI * 16 + nI;
    const size_t slice = (size_t)BATCH * DH;

    // ---- preload W slice (8 panels x 64 rows x 64 cols, hi+lo) ----
    #pragma unroll
    for (int i = 0; i < 16; i++) {
        int u = tid + i * 256;                 // 0..4095
        int p = u >> 9, r = (u >> 3) & 63, g = u & 7;
        u32 so = (u32)(p * 8192 + r * 128 + ((g ^ (r & 7)) * 16));
        size_t go = (size_t)(n0 + r) * KTOT + kb + p * 64 + g * 8;
        CP16(sb + SM_WHI + so, g_whi + go);
        CP16(sb + SM_WLO + so, g_wlo + go);
    }
    CP_COMMIT();
    asm volatile("cp.async.wait_group 0;" ::: "memory");
    __syncthreads();

    for (int t = 0; t < TSTEPS; t++) {
        const int par = t & 1;
        float s[32];

        if (t == 0) {
            #pragma unroll
            for (int i = 0; i < 32; i++) s[i] = 0.f;   // h(0)=0 -> GEMM is 0
        } else {
            // wait for h(t): flags of the 8 producer tiles covering our K-half
            if (tid < 8) {
                const int ft = mI * 16 + kh * 8 + tid;
                int v;
                do {
                    asm volatile("ld.acquire.gpu.global.b32 %0, [%1];"
                                 : "=r"(v) : "l"(g_flag + ft) : "memory");
                } while (v < t);
            }
            __syncthreads();

            const __nv_bfloat16* Ahi0 = g_hhi + (size_t)par * slice;
            const __nv_bfloat16* Alo0 = g_hlo + (size_t)par * slice;

            auto load_chunk = [&](int c) {
                const u32 st = sb + SM_A + (c % 3) * ASTG;
                const int ko = kb + c * KC;
                #pragma unroll
                for (int i = 0; i < 2; i++) {
                    int u = tid + i * 256;         // 0..511
                    int r = u >> 3, g = u & 7;
                    u32 so = (u32)(r * 128 + ((g ^ (r & 7)) * 16));
                    size_t go = (size_t)(m0 + r) * DH + ko + g * 8;
                    CP16(st + so,        Ahi0 + go);
                    CP16(st + 8192 + so, Alo0 + go);
                }
                CP_COMMIT();
            };

            float c0[32], c1[32], c2[32];
            #pragma unroll
            for (int i = 0; i < 32; i++) { c0[i] = 0.f; c1[i] = 0.f; c2[i] = 0.f; }

            load_chunk(0);
            load_chunk(1);
            for (int c = 0; c < 8; c++) {
                if (c < 7) asm volatile("cp.async.wait_group 1;" ::: "memory");
                else       asm volatile("cp.async.wait_group 0;" ::: "memory");
                __syncthreads();
                const u32 stA = sb + SM_A + (c % 3) * ASTG;
                const u32 pW  = sb + SM_WHI + c * 8192;    // panel c
                #pragma unroll
                for (int jj = 0; jj < 2; jj++) {
                    const int j = wk * 2 + jj;
                    u32 ah[2][4], al[2][4], bh[8], bl[8];
                    #pragma unroll
                    for (int tm = 0; tm < 2; tm++) {
                        int row = wm * 32 + tm * 16 + (lane & 15);
                        int g = j * 2 + (lane >> 4);
                        u32 so = (u32)(row * 128 + ((g ^ (row & 7)) * 16));
                        ldsm4(stA + so,        ah[tm][0], ah[tm][1], ah[tm][2], ah[tm][3]);
                        ldsm4(stA + 8192 + so, al[tm][0], al[tm][1], al[tm][2], al[tm][3]);
                    }
                    int rB = wn * 32 + (lane & 7) + ((lane >> 4) & 1) * 8;
                    int gB = j * 2 + ((lane >> 3) & 1);
                    #pragma unroll
                    for (int q = 0; q < 2; q++) {
                        int r = rB + q * 16;
                        u32 so = (u32)(r * 128 + ((gB ^ (r & 7)) * 16));
                        ldsm4(pW + so,         bh[q*4+0], bh[q*4+1], bh[q*4+2], bh[q*4+3]);
                        ldsm4(pW + 65536 + so, bl[q*4+0], bl[q*4+1], bl[q*4+2], bl[q*4+3]);
                    }
                    #pragma unroll
                    for (int tm = 0; tm < 2; tm++)
                        #pragma unroll
                        for (int nt = 0; nt < 4; nt++) {
                            int o = tm * 16 + nt * 4;
                            mma16816(c0 + o, ah[tm], bh[nt*2], bh[nt*2+1]);
                            mma16816(c1 + o, al[tm], bh[nt*2], bh[nt*2+1]);
                            mma16816(c2 + o, ah[tm], bl[nt*2], bl[nt*2+1]);
                        }
                }
                if (c + 2 < 8) load_chunk(c + 2);
            }

            #pragma unroll
            for (int i = 0; i < 32; i++) s[i] = c0[i] + c1[i] + c2[i];

            // intra-CTA reduction across wk groups
            float* red = (float*)(smem + SM_RED);
            if (wk == 1) {
                #pragma unroll
                for (int i = 0; i < 32; i++) red[(wq * 32 + lane) * 32 + i] = s[i];
            }
            __syncthreads();
            if (wk == 0) {
                #pragma unroll
                for (int i = 0; i < 32; i++) s[i] += red[(wq * 32 + lane) * 32 + i];
            }
        }

        // ---- split-K combine (ticket) ----
        float* my = g_part + ((size_t)((tile * 2 + kh) * 2 + par)) * 4096
                  + wid * 1024 + lane * 32;
        if (wk == 0) {
            #pragma unroll
            for (int i = 0; i < 8; i++)
                *(float4*)(my + i * 4) =
                    make_float4(s[i*4], s[i*4+1], s[i*4+2], s[i*4+3]);
        }
        __threadfence();
        __syncthreads();
        if (tid == 0) *roleP = atomicAdd(&g_cnt[tile], 1) - 2 * t;
        __syncthreads();
        const int role = *roleP;

        if (role == 1) {
            __threadfence();
            if (wk == 0) {
                const float* other = g_part
                    + ((size_t)((tile * 2 + (kh ^ 1)) * 2 + par)) * 4096
                    + wid * 1024 + lane * 32;
                #pragma unroll
                for (int i = 0; i < 8; i++) {
                    float4 o = *(const float4*)(other + i * 4);
                    s[i*4] += o.x; s[i*4+1] += o.y; s[i*4+2] += o.z; s[i*4+3] += o.w;
                }
                // epilogue: h(t+1) = tanh(s + Z[t])
                float* outN = out + (size_t)(t + 1) * slice;
                __nv_bfloat16* hh0 = g_hhi + (size_t)(par ^ 1) * slice;
                __nv_bfloat16* hl0 = g_hlo + (size_t)(par ^ 1) * slice;
                #pragma unroll
                for (int tm = 0; tm < 2; tm++)
                    #pragma unroll
                    for (int nt = 0; nt < 4; nt++) {
                        const int col = n0 + wn * 32 + nt * 8 + (lane & 3) * 2;
                        #pragma unroll
                        for (int hf = 0; hf < 2; hf++) {
                            const int row = m0 + wm * 32 + tm * 16 + (lane >> 2) + hf * 8;
                            const int o = tm * 16 + nt * 4 + hf * 2;
                            const size_t zi = ((size_t)t * BATCH + row) * DH + col;
                            float2 zv = *(const float2*)(g_Z + zi);
                            float z0 = s[o]   + zv.x;
                            float z1 = s[o+1] + zv.y;
                            float e0 = __expf(2.0f * z0), e1 = __expf(2.0f * z1);
                            float h0 = 1.0f - 2.0f / (e0 + 1.0f);
                            float h1 = 1.0f - 2.0f / (e1 + 1.0f);
                            *(float2*)(outN + (size_t)row * DH + col) = make_float2(h0, h1);
                            __nv_bfloat16 p0 = __float2bfloat16(h0), p1 = __float2bfloat16(h1);
                            __nv_bfloat162 hi2; hi2.x = p0; hi2.y = p1;
                            __nv_bfloat162 lo2;
                            lo2.x = __float2bfloat16(h0 - __bfloat162float(p0));
                            lo2.y = __float2bfloat16(h1 - __bfloat162float(p1));
                            *(__nv_bfloat162*)(hh0 + (size_t)row * DH + col) = hi2;
                            *(__nv_bfloat162*)(hl0 + (size_t)row * DH + col) = lo2;
                        }
                    }
            }
        }
        __threadfence();
        __syncthreads();
        if (role == 1 && tid == 0)
            atomicExch(&g_flag[tile], t + 1);   // h(t+1) ready
    }
}

extern "C" void kernel_launch(void* const* d_in, const int* in_sizes, int n_in,
                              void* d_out, int out_size) {
    const float* seq = (const float*)d_in[0];   // (T, B, DIN)
    const float* W   = (const float*)d_in[1];   // (DH, KTOT)
    const float* b   = (const float*)d_in[2];   // (DH,)
    float* out = (float*)d_out;                 // (T+1, B, DH)
    (void)in_sizes; (void)n_in; (void)out_size;

    cudaFuncSetAttribute(precompute_z, cudaFuncAttributeMaxDynamicSharedMemorySize, SMEM2);
    cudaFuncSetAttribute(rnn_persist, cudaFuncAttributeMaxDynamicSharedMemorySize, SMEMP);

    split_w<<<(DH * KTOT) / 256, 256>>>(W);
    split_x<<<(TSTEPS * BATCH * DIN) / 256, 256>>>(seq);
    init_h<<<(BATCH * DH) / 256, 256>>>(out);

    dim3 pgrid(DH / 64, (TSTEPS * BATCH) / 128);   // (16, 512)
    precompute_z<<<pgrid, 256, SMEM2>>>(b);

    rnn_persist<<<128, 256, SMEMP>>>(out);
}

// round 7
// speedup vs baseline: 1.8229x; 1.8229x over previous
#include <cuda_runtime.h>
#include <cuda_bf16.h>
#include <cstdint>

// RNN_438086664357: h_{t+1} = tanh(W [h_t ; x_t] + b)
// Round 7: Z = x@Wx^T+b precomputed (proven 67.8% tensor kernel); per-step
// kernel is R3's proven engine with K=1024 (h-part only) + Z in epilogue.

#define TSTEPS 256
#define BATCH  256
#define DH     1024
#define DIN    1024
#define KTOT   2048
#define KC     64
#define NCH    16              // K=1024 / 64

typedef unsigned int u32;

// step stage: Ahi 4K | Alo 4K | Whi 8K | Wlo 8K
#define SOFF_ALO  4096
#define SOFF_WHI  8192
#define SOFF_WLO  16384
#define STG1      24576
#define SMEM1     (3 * STG1)      // 72 KB

// precompute stage: Ahi 16K | Alo 16K | Whi 8K | Wlo 8K
#define SOFF2_ALO 16384
#define SOFF2_WHI 32768
#define SOFF2_WLO 40960
#define STG2      49152
#define SMEM2     (3 * STG2)      // 144 KB

// ---- device scratch ----
__device__ __nv_bfloat16 g_xhi[(size_t)TSTEPS * BATCH * DIN];
__device__ __nv_bfloat16 g_xlo[(size_t)TSTEPS * BATCH * DIN];
__device__ __nv_bfloat16 g_whi[(size_t)DH * KTOT];
__device__ __nv_bfloat16 g_wlo[(size_t)DH * KTOT];
__device__ __nv_bfloat16 g_hhi[2 * (size_t)BATCH * DH];
__device__ __nv_bfloat16 g_hlo[2 * (size_t)BATCH * DH];
__device__ float g_Z[(size_t)TSTEPS * BATCH * DH];

__device__ __forceinline__ u32 s2u(const void* p) {
    u32 a;
    asm("{ .reg .u64 t; cvta.to.shared.u64 t, %1; cvt.u32.u64 %0, t; }"
        : "=r"(a) : "l"(p));
    return a;
}

#define CP16(sm, gp) asm volatile("cp.async.cg.shared.global [%0], [%1], 16;" :: "r"(sm), "l"(gp))
#define CP_COMMIT()  asm volatile("cp.async.commit_group;" ::: "memory")

__device__ __forceinline__ void ldsm4(u32 a, u32& r0, u32& r1, u32& r2, u32& r3) {
    asm volatile("ldmatrix.sync.aligned.m8n8.x4.shared.b16 {%0,%1,%2,%3}, [%4];"
                 : "=r"(r0), "=r"(r1), "=r"(r2), "=r"(r3) : "r"(a));
}

__device__ __forceinline__ void mma16816(float* c, const u32* a, u32 b0, u32 b1) {
    asm volatile(
        "mma.sync.aligned.m16n8k16.row.col.f32.bf16.bf16.f32 "
        "{%0,%1,%2,%3}, {%4,%5,%6,%7}, {%8,%9}, {%0,%1,%2,%3};"
        : "+f"(c[0]), "+f"(c[1]), "+f"(c[2]), "+f"(c[3])
        : "r"(a[0]), "r"(a[1]), "r"(a[2]), "r"(a[3]), "r"(b0), "r"(b1));
}

// ---- setup kernels ----
__global__ void split_w(const float* __restrict__ W) {
    int i = blockIdx.x * blockDim.x + threadIdx.x;
    float v = W[i];
    __nv_bfloat16 h = __float2bfloat16(v);
    g_whi[i] = h;
    g_wlo[i] = __float2bfloat16(v - __bfloat162float(h));
}

__global__ void split_x(const float* __restrict__ X) {
    size_t i = (size_t)blockIdx.x * blockDim.x + threadIdx.x;
    float v = X[i];
    __nv_bfloat16 h = __float2bfloat16(v);
    g_xhi[i] = h;
    g_xlo[i] = __float2bfloat16(v - __bfloat162float(h));
}

__global__ void init_out0(float* __restrict__ out0) {
    out0[blockIdx.x * blockDim.x + threadIdx.x] = 0.0f;
}

// ---- precompute Z = x @ Wx^T + b (proven: 67.8% tensor) ----
__global__ void __launch_bounds__(256, 1)
precompute_z(const float* __restrict__ bias)
{
    extern __shared__ char smem[];
    const u32 sb = s2u(smem);
    const int tid = threadIdx.x, wid = tid >> 5, lane = tid & 31;
    const int wm = wid & 3, wn = wid >> 2;
    const int n0 = blockIdx.x * 64;
    const int mg = blockIdx.y * 128;

    auto load_chunk = [&](int c, int s) {
        const u32 st = sb + s * STG2;
        const int ko = c * KC;
        #pragma unroll
        for (int i = 0; i < 4; i++) {
            int unit = tid + i * 256;
            int r = unit >> 3, g = unit & 7;
            u32 so = (u32)(r * 128 + ((g ^ (r & 7)) * 16));
            size_t go = (size_t)(mg + r) * DIN + ko + g * 8;
            CP16(st + so,             g_xhi + go);
            CP16(st + SOFF2_ALO + so, g_xlo + go);
        }
        #pragma unroll
        for (int i = 0; i < 2; i++) {
            int unit = tid + i * 256;
            int r = unit >> 3, g = unit & 7;
            u32 so = (u32)(r * 128 + ((g ^ (r & 7)) * 16));
            size_t go = (size_t)(n0 + r) * KTOT + DH + ko + g * 8;
            CP16(st + SOFF2_WHI + so, g_whi + go);
            CP16(st + SOFF2_WLO + so, g_wlo + go);
        }
        CP_COMMIT();
    };

    float c0[32], c1[32], c2[32];
    #pragma unroll
    for (int i = 0; i < 32; i++) { c0[i] = 0.f; c1[i] = 0.f; c2[i] = 0.f; }

    load_chunk(0, 0);
    load_chunk(1, 1);
    for (int c = 0; c < 16; c++) {
        if (c < 15) asm volatile("cp.async.wait_group 1;" ::: "memory");
        else        asm volatile("cp.async.wait_group 0;" ::: "memory");
        __syncthreads();
        const u32 st = sb + (c % 3) * STG2;
        #pragma unroll
        for (int j = 0; j < 4; j++) {
            u32 ah[2][4], al[2][4], bh[8], bl[8];
            #pragma unroll
            for (int tm = 0; tm < 2; tm++) {
                int row = wm * 32 + tm * 16 + (lane & 15);
                int g = j * 2 + (lane >> 4);
                u32 so = (u32)(row * 128 + ((g ^ (row & 7)) * 16));
                ldsm4(st + so,             ah[tm][0], ah[tm][1], ah[tm][2], ah[tm][3]);
                ldsm4(st + SOFF2_ALO + so, al[tm][0], al[tm][1], al[tm][2], al[tm][3]);
            }
            int rB = wn * 32 + (lane & 7) + ((lane >> 4) & 1) * 8;
            int gB = j * 2 + ((lane >> 3) & 1);
            #pragma unroll
            for (int q = 0; q < 2; q++) {
                int r = rB + q * 16;
                u32 so = (u32)(r * 128 + ((gB ^ (r & 7)) * 16));
                ldsm4(st + SOFF2_WHI + so, bh[q*4+0], bh[q*4+1], bh[q*4+2], bh[q*4+3]);
                ldsm4(st + SOFF2_WLO + so, bl[q*4+0], bl[q*4+1], bl[q*4+2], bl[q*4+3]);
            }
            #pragma unroll
            for (int tm = 0; tm < 2; tm++)
                #pragma unroll
                for (int nt = 0; nt < 4; nt++) {
                    int o = tm * 16 + nt * 4;
                    mma16816(c0 + o, ah[tm], bh[nt*2], bh[nt*2+1]);
                    mma16816(c1 + o, al[tm], bh[nt*2], bh[nt*2+1]);
                    mma16816(c2 + o, ah[tm], bl[nt*2], bl[nt*2+1]);
                }
        }
        if (c + 2 < 16) load_chunk(c + 2, (c + 2) % 3);
    }

    #pragma unroll
    for (int tm = 0; tm < 2; tm++)
        #pragma unroll
        for (int nt = 0; nt < 4; nt++) {
            const int col = n0 + wn * 32 + nt * 8 + (lane & 3) * 2;
            const float b0 = __ldg(bias + col), b1 = __ldg(bias + col + 1);
            #pragma unroll
            for (int hf = 0; hf < 2; hf++) {
                const int row = mg + wm * 32 + tm * 16 + (lane >> 2) + hf * 8;
                const int o = tm * 16 + nt * 4 + hf * 2;
                float z0 = c0[o]   + c1[o]   + c2[o]   + b0;
                float z1 = c0[o+1] + c1[o+1] + c2[o+1] + b1;
                *(float2*)(g_Z + (size_t)row * DH + col) = make_float2(z0, z1);
            }
        }
}

// ---- per-step: s = h @ Wh^T (K=1024); h' = tanh(s + Z[t]) ----
// grid (16 n, 8 m); CTA tile (32m, 64n); 4 warps 2x2, warp tile m16n32.
__global__ void __launch_bounds__(128, 1)
rnn_step(float* __restrict__ outNext, int t, int parity)
{
    extern __shared__ char smem[];
    const u32 sb = s2u(smem);
    const int tid = threadIdx.x, wid = tid >> 5, lane = tid & 31;
    const int wm = wid & 1, wn = wid >> 1;
    const int n0 = blockIdx.x * 64, m0 = blockIdx.y * 32;

    float c0[16], c1[16], c2[16];
    #pragma unroll
    for (int i = 0; i < 16; i++) { c0[i] = 0.f; c1[i] = 0.f; c2[i] = 0.f; }

    if (t > 0) {
        const __nv_bfloat16* Ahi0 = g_hhi + (size_t)parity * BATCH * DH;
        const __nv_bfloat16* Alo0 = g_hlo + (size_t)parity * BATCH * DH;
        const int lr = tid >> 3, lg = tid & 7;

        auto load_chunk = [&](int c, int s) {
            const u32 st = sb + s * STG1;
            const int ko = c * KC;
            #pragma unroll
            for (int u = 0; u < 2; u++) {       // A: 32 rows, hi+lo
                int r = lr + u * 16;
                u32 so = (u32)(r * 128 + ((lg ^ (r & 7)) * 16));
                size_t go = (size_t)(m0 + r) * DH + ko + lg * 8;
                CP16(st + so,            Ahi0 + go);
                CP16(st + SOFF_ALO + so, Alo0 + go);
            }
            #pragma unroll
            for (int u = 0; u < 4; u++) {       // W: 64 rows, hi+lo
                int r = lr + u * 16;
                u32 so = (u32)(r * 128 + ((lg ^ (r & 7)) * 16));
                size_t go = (size_t)(n0 + r) * KTOT + ko + lg * 8;
                CP16(st + SOFF_WHI + so, g_whi + go);
                CP16(st + SOFF_WLO + so, g_wlo + go);
            }
            CP_COMMIT();
        };

        const int aRow  = wm * 16 + (lane & 15);
        const int aHi   = (lane >> 4);
        const int bRow0 = wn * 32 + (lane & 7) + ((lane >> 4) & 1) * 8;
        const int bHi   = (lane >> 3) & 1;

        load_chunk(0, 0);
        load_chunk(1, 1);
        for (int c = 0; c < NCH; c++) {
            if (c < NCH - 1) asm volatile("cp.async.wait_group 1;" ::: "memory");
            else             asm volatile("cp.async.wait_group 0;" ::: "memory");
            __syncthreads();
            const u32 st = sb + (c % 3) * STG1;
            #pragma unroll
            for (int j = 0; j < 4; j++) {
                u32 ah[4], al[4], bh[8], bl[8];
                {
                    int g = j * 2 + aHi;
                    u32 so = (u32)(aRow * 128 + ((g ^ (aRow & 7)) * 16));
                    ldsm4(st + so,            ah[0], ah[1], ah[2], ah[3]);
                    ldsm4(st + SOFF_ALO + so, al[0], al[1], al[2], al[3]);
                }
                #pragma unroll
                for (int q = 0; q < 2; q++) {
                    int r = bRow0 + q * 16;
                    int g = j * 2 + bHi;
                    u32 so = (u32)(r * 128 + ((g ^ (r & 7)) * 16));
                    ldsm4(st + SOFF_WHI + so, bh[q*4+0], bh[q*4+1], bh[q*4+2], bh[q*4+3]);
                    ldsm4(st + SOFF_WLO + so, bl[q*4+0], bl[q*4+1], bl[q*4+2], bl[q*4+3]);
                }
                #pragma unroll
                for (int nt = 0; nt < 4; nt++) {
                    mma16816(c0 + nt * 4, ah, bh[nt*2], bh[nt*2+1]);
                    mma16816(c1 + nt * 4, al, bh[nt*2], bh[nt*2+1]);
                    mma16816(c2 + nt * 4, ah, bl[nt*2], bl[nt*2+1]);
                }
            }
            if (c + 2 < NCH) load_chunk(c + 2, (c + 2) % 3);
        }
    }

    // epilogue: h' = tanh(acc + Z[t]); write fp32 out + bf16 hi/lo state
    __nv_bfloat16* hh0 = g_hhi + (size_t)(parity ^ 1) * BATCH * DH;
    __nv_bfloat16* hl0 = g_hlo + (size_t)(parity ^ 1) * BATCH * DH;
    const int rL = lane >> 2, cL = (lane & 3) * 2;
    #pragma unroll
    for (int nt = 0; nt < 4; nt++) {
        const int col = n0 + wn * 32 + nt * 8 + cL;
        #pragma unroll
        for (int hf = 0; hf < 2; hf++) {
            const int row = m0 + wm * 16 + rL + hf * 8;
            const int o = nt * 4 + hf * 2;
            const size_t zi = ((size_t)t * BATCH + row) * DH + col;
            const float2 zv = *(const float2*)(g_Z + zi);
            float z0 = c0[o]   + c1[o]   + c2[o]   + zv.x;
            float z1 = c0[o+1] + c1[o+1] + c2[o+1] + zv.y;
            float e0 = __expf(2.0f * z0), e1 = __expf(2.0f * z1);
            float h0 = 1.0f - 2.0f / (e0 + 1.0f);
            float h1 = 1.0f - 2.0f / (e1 + 1.0f);
            *(float2*)(outNext + (size_t)row * DH + col) = make_float2(h0, h1);
            __nv_bfloat16 p0 = __float2bfloat16(h0), p1 = __float2bfloat16(h1);
            __nv_bfloat162 hi2; hi2.x = p0; hi2.y = p1;
            __nv_bfloat162 lo2;
            lo2.x = __float2bfloat16(h0 - __bfloat162float(p0));
            lo2.y = __float2bfloat16(h1 - __bfloat162float(p1));
            *(__nv_bfloat162*)(hh0 + (size_t)row * DH + col) = hi2;
            *(__nv_bfloat162*)(hl0 + (size_t)row * DH + col) = lo2;
        }
    }
}

extern "C" void kernel_launch(void* const* d_in, const int* in_sizes, int n_in,
                              void* d_out, int out_size) {
    const float* seq = (const float*)d_in[0];   // (T, B, DIN)
    const float* W   = (const float*)d_in[1];   // (DH, KTOT)
    const float* b   = (const float*)d_in[2];   // (DH,)
    float* out = (float*)d_out;                 // (T+1, B, DH)
    (void)in_sizes; (void)n_in; (void)out_size;

    cudaFuncSetAttribute(precompute_z, cudaFuncAttributeMaxDynamicSharedMemorySize, SMEM2);
    cudaFuncSetAttribute(rnn_step, cudaFuncAttributeMaxDynamicSharedMemorySize, SMEM1);

    const size_t slice = (size_t)BATCH * DH;

    split_w<<<(DH * KTOT) / 256, 256>>>(W);
    split_x<<<(TSTEPS * BATCH * DIN) / 256, 256>>>(seq);
    init_out0<<<(BATCH * DH) / 256, 256>>>(out);

    dim3 pgrid(DH / 64, (TSTEPS * BATCH) / 128);   // (16, 512)
    precompute_z<<<pgrid, 256, SMEM2>>>(b);

    dim3 grid(16, 8);                               // 128 CTAs
    for (int t = 0; t < TSTEPS; t++) {
        rnn_step<<<grid, 128, SMEM1>>>(out + (t + 1) * slice, t, t & 1);
    }
}